// round 4
// baseline (speedup 1.0000x reference)
#include <cuda_runtime.h>

// Bilinear 2x upsample, half_pixel_centers=False (asymmetric: h = hd/2).
// Input : (16, 64, 128, 128) fp32  -> flattened NC=1024 images of 128x128
// Output: (16, 64, 256, 256) fp32
//
// Exact stencil (reference-equivalent, neighbor clamped at 127):
//   out[2i  ][2j  ] = a
//   out[2i  ][2j+1] = (a + b)/2          b = x[i][j+1]
//   out[2i+1][2j  ] = (a + c)/2          c = x[i+1][j]
//   out[2i+1][2j+1] = ((a+c)/2 + (b+d)/2)/2
//
// One warp per (nc, input row). Lane l owns input cols [4l, 4l+3] via float4,
// produces output cols [8l, 8l+7] of both output rows (4x float4 stores).

static constexpr int SRC_H = 128;
static constexpr int SRC_W = 128;
static constexpr int NC    = 16 * 64;   // 1024
static constexpr int DST_H = 256;
static constexpr int DST_W = 256;

__global__ void __launch_bounds__(256)
bilinear2x_kernel(const float* __restrict__ in, float* __restrict__ out) {
    const int warp_global = blockIdx.x * (blockDim.x >> 5) + (threadIdx.x >> 5);
    const int lane = threadIdx.x & 31;

    const int nc = warp_global >> 7;          // / SRC_H
    const int i  = warp_global & (SRC_H - 1); // input row

    const float* img = in + (size_t)nc * (SRC_H * SRC_W);
    const int i1 = (i < SRC_H - 1) ? (i + 1) : i;   // clamp bottom row

    // Load 4 contiguous input pixels of row i and row i+1 (clamped).
    const float4 a = __ldg(reinterpret_cast<const float4*>(img + i  * SRC_W) + lane);
    const float4 c = __ldg(reinterpret_cast<const float4*>(img + i1 * SRC_W) + lane);

    // Right neighbor of this thread's last element (from lane+1; lane 31 clamps).
    float a4 = __shfl_down_sync(0xffffffffu, a.x, 1);
    float c4 = __shfl_down_sync(0xffffffffu, c.x, 1);
    if (lane == 31) { a4 = a.w; c4 = c.w; }

    // Even output row 2i: horizontal interp of row i.
    const float4 e0 = make_float4(a.x, 0.5f * (a.x + a.y),
                                  a.y, 0.5f * (a.y + a.z));
    const float4 e1 = make_float4(a.z, 0.5f * (a.z + a.w),
                                  a.w, 0.5f * (a.w + a4));

    // Vertical midpoints, then horizontal interp for odd output row 2i+1.
    const float mx = 0.5f * (a.x + c.x);
    const float my = 0.5f * (a.y + c.y);
    const float mz = 0.5f * (a.z + c.z);
    const float mw = 0.5f * (a.w + c.w);
    const float m4 = 0.5f * (a4 + c4);

    const float4 o0 = make_float4(mx, 0.5f * (mx + my),
                                  my, 0.5f * (my + mz));
    const float4 o1 = make_float4(mz, 0.5f * (mz + mw),
                                  mw, 0.5f * (mw + m4));

    float* outImg = out + (size_t)nc * (DST_H * DST_W);
    float4* r0 = reinterpret_cast<float4*>(outImg + (2 * i)     * DST_W + 8 * lane);
    float4* r1 = reinterpret_cast<float4*>(outImg + (2 * i + 1) * DST_W + 8 * lane);
    r0[0] = e0;
    r0[1] = e1;
    r1[0] = o0;
    r1[1] = o1;
}

extern "C" void kernel_launch(void* const* d_in, const int* in_sizes, int n_in,
                              void* d_out, int out_size) {
    const float* x = (const float*)d_in[0];
    float* out = (float*)d_out;

    // One warp per (nc, input row): NC * SRC_H warps total.
    const int total_warps = NC * SRC_H;          // 131072
    const int threads = 256;                     // 8 warps/block
    const int blocks = total_warps / (threads / 32);  // 16384

    bilinear2x_kernel<<<blocks, threads>>>(x, out);
}

// round 5
// speedup vs baseline: 1.0728x; 1.0728x over previous
#include <cuda_runtime.h>

// Bilinear 2x upsample, half_pixel_centers=False (asymmetric: h = hd/2).
// Input : (16, 64, 128, 128) fp32, Output: (16, 64, 256, 256) fp32.
//
// Exact stencil (neighbors clamped at index 127):
//   out[2i  ][2j  ] = x[i][j]
//   out[2i  ][2j+1] = (x[i][j] + x[i][j+1]) / 2
//   out[2i+1][2j  ] = (x[i][j] + x[i+1][j]) / 2
//   out[2i+1][2j+1] = (x[i][j]+x[i][j+1]+x[i+1][j]+x[i+1][j+1]) / 4
//
// One warp per (nc, input row i). Fully-coalesced layout:
//   loads : lane l reads float2 at input cols (2l) and (64+2l) of rows i, i+1
//           -> each LDG.64 instruction is a contiguous 256B warp transaction
//   stores: lane l writes float4 at output cols (4l) and (128+4l) of rows
//           2i, 2i+1 -> each STG.128 instruction is a contiguous 512B warp
//           transaction (exactly 4 cache lines), no L1 wavefront amplification.

static constexpr int SRC_H = 128;
static constexpr int SRC_W = 128;
static constexpr int NC    = 16 * 64;   // 1024
static constexpr int DST_W = 256;

__global__ void __launch_bounds__(256)
bilinear2x_kernel(const float* __restrict__ in, float* __restrict__ out) {
    const unsigned F = 0xffffffffu;
    const int warp_global = blockIdx.x * (blockDim.x >> 5) + (threadIdx.x >> 5);
    const int lane = threadIdx.x & 31;

    const int nc = warp_global >> 7;          // / SRC_H
    const int i  = warp_global & (SRC_H - 1); // input row

    const float* img = in + (size_t)nc * (SRC_H * SRC_W);
    const int i1 = (i < SRC_H - 1) ? (i + 1) : i;   // clamp bottom row

    const float2* rowA = reinterpret_cast<const float2*>(img + i  * SRC_W);
    const float2* rowC = reinterpret_cast<const float2*>(img + i1 * SRC_W);

    // Two coalesced float2 loads per row: cols (2l,2l+1) and (64+2l,64+2l+1)
    const float2 a0 = __ldg(rowA + lane);
    const float2 a1 = __ldg(rowA + 32 + lane);
    const float2 c0 = __ldg(rowC + lane);
    const float2 c1 = __ldg(rowC + 32 + lane);

    const int nxt = (lane + 1) & 31;

    // Right neighbor of half 0 (input col 2l+2):
    //   lanes 0..30 -> lane+1's a0.x ; lane 31 -> col 64 = lane 0's a1.x
    const float sa0 = __shfl_sync(F, a0.x, nxt);
    const float sc0 = __shfl_sync(F, c0.x, nxt);
    const float ta  = __shfl_sync(F, a1.x, 0);
    const float tc  = __shfl_sync(F, c1.x, 0);
    const float na0 = (lane == 31) ? ta : sa0;
    const float nc0 = (lane == 31) ? tc : sc0;

    // Right neighbor of half 1 (input col 64+2l+2):
    //   lanes 0..30 -> lane+1's a1.x ; lane 31 -> col 128 clamps to 127 (own .y)
    const float sa1 = __shfl_sync(F, a1.x, nxt);
    const float sc1 = __shfl_sync(F, c1.x, nxt);
    const float na1 = (lane == 31) ? a1.y : sa1;
    const float nc1 = (lane == 31) ? c1.y : sc1;

    // Even output row 2i (horizontal interp of row i)
    const float4 e0 = make_float4(a0.x, 0.5f * (a0.x + a0.y),
                                  a0.y, 0.5f * (a0.y + na0));
    const float4 e1 = make_float4(a1.x, 0.5f * (a1.x + a1.y),
                                  a1.y, 0.5f * (a1.y + na1));

    // Odd output row 2i+1: vertical midpoints then horizontal interp
    const float m0x = 0.5f * (a0.x + c0.x);
    const float m0y = 0.5f * (a0.y + c0.y);
    const float m0n = 0.5f * (na0 + nc0);
    const float m1x = 0.5f * (a1.x + c1.x);
    const float m1y = 0.5f * (a1.y + c1.y);
    const float m1n = 0.5f * (na1 + nc1);

    const float4 o0 = make_float4(m0x, 0.5f * (m0x + m0y),
                                  m0y, 0.5f * (m0y + m0n));
    const float4 o1 = make_float4(m1x, 0.5f * (m1x + m1y),
                                  m1y, 0.5f * (m1y + m1n));

    float* outImg = out + (size_t)nc * (2 * SRC_H * DST_W);
    float4* r0 = reinterpret_cast<float4*>(outImg + (2 * i)     * DST_W);
    float4* r1 = reinterpret_cast<float4*>(outImg + (2 * i + 1) * DST_W);

    // Four fully-coalesced 512B warp stores; streaming hint (output never re-read)
    __stcs(r0 + lane,      e0);
    __stcs(r0 + 32 + lane, e1);
    __stcs(r1 + lane,      o0);
    __stcs(r1 + 32 + lane, o1);
}

extern "C" void kernel_launch(void* const* d_in, const int* in_sizes, int n_in,
                              void* d_out, int out_size) {
    const float* x = (const float*)d_in[0];
    float* out = (float*)d_out;

    const int total_warps = NC * SRC_H;               // 131072
    const int threads = 256;                          // 8 warps/block
    const int blocks = total_warps / (threads / 32);  // 16384

    bilinear2x_kernel<<<blocks, threads>>>(x, out);
}

// round 6
// speedup vs baseline: 1.0741x; 1.0012x over previous
#include <cuda_runtime.h>

// Bilinear 2x upsample, half_pixel_centers=False (asymmetric: h = hd/2).
// Input : (16, 64, 128, 128) fp32, Output: (16, 64, 256, 256) fp32.
//
// Stencil (exact, neighbors clamped at 127):
//   out[2i  ][2j  ] = x[i][j]
//   out[2i  ][2j+1] = (x[i][j] + x[i][j+1]) / 2
//   out[2i+1][*]    = average of rows out[2i][*]-expansion of x[i] and x[i+1]
//   (horizontal interp H is linear, so odd rows = (H(row_i)+H(row_{i+1}))/2)
//
// One warp per input ROW PAIR (2r, 2r+1): loads rows 2r, 2r+1, 2r+2 (clamped),
// emits output rows 4r..4r+3. 6 independent coalesced float2 loads up front
// (maximum MLP), 8 fully-coalesced 512B float4 warp stores.

static constexpr int SRC_H = 128;
static constexpr int SRC_W = 128;
static constexpr int NC    = 16 * 64;   // 1024
static constexpr int DST_W = 256;

struct RowData {
    float2 v0, v1;   // cols (2l, 2l+1) and (64+2l, 64+2l+1)
    float  n0, n1;   // right neighbors: cols 2l+2 and 64+2l+2 (clamped)
};

// Horizontal 2x expansion of one input row half-pair -> two float4 (8 out cols)
__device__ __forceinline__ void h_expand(const RowData& r, float4& e0, float4& e1) {
    e0 = make_float4(r.v0.x, 0.5f * (r.v0.x + r.v0.y),
                     r.v0.y, 0.5f * (r.v0.y + r.n0));
    e1 = make_float4(r.v1.x, 0.5f * (r.v1.x + r.v1.y),
                     r.v1.y, 0.5f * (r.v1.y + r.n1));
}

__device__ __forceinline__ float4 avg4(const float4& a, const float4& b) {
    return make_float4(0.5f * (a.x + b.x), 0.5f * (a.y + b.y),
                       0.5f * (a.z + b.z), 0.5f * (a.w + b.w));
}

__global__ void __launch_bounds__(256)
bilinear2x_kernel(const float* __restrict__ in, float* __restrict__ out) {
    const unsigned F = 0xffffffffu;
    const int warp_global = blockIdx.x * (blockDim.x >> 5) + (threadIdx.x >> 5);
    const int lane = threadIdx.x & 31;

    const int nc = warp_global >> 6;        // / 64 row-pairs per image
    const int r  = warp_global & 63;        // row-pair index
    const int iA = 2 * r;                   // input rows
    const int iB = 2 * r + 1;
    const int iC = (iB < SRC_H - 1) ? (iB + 1) : iB;   // clamp bottom

    const float* img = in + (size_t)nc * (SRC_H * SRC_W);
    const float2* rowA = reinterpret_cast<const float2*>(img + iA * SRC_W);
    const float2* rowB = reinterpret_cast<const float2*>(img + iB * SRC_W);
    const float2* rowC = reinterpret_cast<const float2*>(img + iC * SRC_W);

    // Front-batch all 6 independent coalesced loads (256B warp transactions)
    RowData A, B, C;
    A.v0 = __ldg(rowA + lane);      A.v1 = __ldg(rowA + 32 + lane);
    B.v0 = __ldg(rowB + lane);      B.v1 = __ldg(rowB + 32 + lane);
    C.v0 = __ldg(rowC + lane);      C.v1 = __ldg(rowC + 32 + lane);

    const int nxt = (lane + 1) & 31;

    // Right-neighbor resolution per row:
    //   half 0: lanes 0..30 -> lane+1's v0.x ; lane 31 -> col 64 = lane 0's v1.x
    //   half 1: lanes 0..30 -> lane+1's v1.x ; lane 31 -> clamp to own v1.y
    {
        float s0 = __shfl_sync(F, A.v0.x, nxt);
        float s1 = __shfl_sync(F, A.v1.x, nxt);
        float t  = __shfl_sync(F, A.v1.x, 0);
        A.n0 = (lane == 31) ? t : s0;
        A.n1 = (lane == 31) ? A.v1.y : s1;
    }
    {
        float s0 = __shfl_sync(F, B.v0.x, nxt);
        float s1 = __shfl_sync(F, B.v1.x, nxt);
        float t  = __shfl_sync(F, B.v1.x, 0);
        B.n0 = (lane == 31) ? t : s0;
        B.n1 = (lane == 31) ? B.v1.y : s1;
    }
    {
        float s0 = __shfl_sync(F, C.v0.x, nxt);
        float s1 = __shfl_sync(F, C.v1.x, nxt);
        float t  = __shfl_sync(F, C.v1.x, 0);
        C.n0 = (lane == 31) ? t : s0;
        C.n1 = (lane == 31) ? C.v1.y : s1;
    }

    // Horizontal expansions of the three input rows
    float4 eA0, eA1, eB0, eB1, eC0, eC1;
    h_expand(A, eA0, eA1);
    h_expand(B, eB0, eB1);
    h_expand(C, eC0, eC1);

    float* outImg = out + (size_t)nc * (2 * SRC_H * DST_W);
    float4* o0 = reinterpret_cast<float4*>(outImg + (4 * r + 0) * DST_W);
    float4* o1 = reinterpret_cast<float4*>(outImg + (4 * r + 1) * DST_W);
    float4* o2 = reinterpret_cast<float4*>(outImg + (4 * r + 2) * DST_W);
    float4* o3 = reinterpret_cast<float4*>(outImg + (4 * r + 3) * DST_W);

    // 8 fully-coalesced 512B warp stores; streaming (output never re-read)
    __stcs(o0 + lane,      eA0);
    __stcs(o0 + 32 + lane, eA1);
    __stcs(o1 + lane,      avg4(eA0, eB0));
    __stcs(o1 + 32 + lane, avg4(eA1, eB1));
    __stcs(o2 + lane,      eB0);
    __stcs(o2 + 32 + lane, eB1);
    __stcs(o3 + lane,      avg4(eB0, eC0));
    __stcs(o3 + 32 + lane, avg4(eB1, eC1));
}

extern "C" void kernel_launch(void* const* d_in, const int* in_sizes, int n_in,
                              void* d_out, int out_size) {
    const float* x = (const float*)d_in[0];
    float* out = (float*)d_out;

    const int total_warps = NC * (SRC_H / 2);         // 65536 row-pairs
    const int threads = 256;                          // 8 warps/block
    const int blocks = total_warps / (threads / 32);  // 8192

    bilinear2x_kernel<<<blocks, threads>>>(x, out);
}